// round 14
// baseline (speedup 1.0000x reference)
#include <cuda_runtime.h>

#define NGRID 10000
#define NSTEP 365
#define NMUL 16
#define NEARZERO 1e-5f
#define TBATCH 5            // 365 = 5 * 73
#define NBATCH (NSTEP / TBATCH)
#define XSTRIDE (NGRID * 3)
#define RSTRIDE 36          // smem row stride (floats): 32 data + 4 pad

struct Forc { float P[TBATCH], T[TBATCH], E[TBATCH]; };

__device__ __forceinline__ void load_batch(const float* __restrict__ xb, int tb, Forc& f) {
    const float* a = xb + (size_t)tb * TBATCH * XSTRIDE;
    #pragma unroll
    for (int k = 0; k < TBATCH; ++k) {
        f.P[k] = __ldg(a + 0);
        f.T[k] = __ldg(a + 1);
        f.E[k] = __ldg(a + 2);
        a += XSTRIDE;
    }
}

__global__ __launch_bounds__(32)
void hbv_waterloss_kernel(
    const float* __restrict__ x,     // (365, 10000, 3) P,T,PET
    const float* __restrict__ praw,  // (365, 10000, 3, 16) -- only step 364 used
    const float* __restrict__ wraw,  // (10000, 13, 16)
    const float* __restrict__ ac,    // (10000,)
    float* __restrict__ out)         // (365, 10000)
{
    __shared__ float red[2][TBATCH * RSTRIDE];

    const int lane = threadIdx.x;                  // 0..31
    const int tid  = blockIdx.x * 32 + lane;
    const int g = tid >> 4;        // grid cell (lanes 0-15 -> g0, 16-31 -> g0+1)
    const int m = tid & 15;        // multiplier index

    // ---- parameter scaling (HBV params from last timestep: static_idx = -1) ----
    const float* pr = praw + ((size_t)364 * NGRID + g) * (3 * NMUL) + m;
    const float parBETA   = 1.0f  + pr[0]      * 5.0f;
    const float parK0     = 0.05f + pr[16]     * 0.85f;
    const float parBETAET = 0.3f  + pr[32]     * 4.7f;

    const float* wr = wraw + (size_t)g * (13 * NMUL) + m;
    const float parFC    = 50.0f  + wr[0]   * 950.0f;
    const float parK1    = 0.01f  + wr[16]  * 0.49f;
    const float parK2    = 0.001f + wr[32]  * 0.199f;
    const float parLP    = 0.2f   + wr[48]  * 0.8f;
    const float parPERC  =          wr[64]  * 10.0f;
    const float parUZL   =          wr[80]  * 100.0f;
    const float parTT    = -2.5f  + wr[96]  * 5.0f;
    const float parCFMAX = 0.5f   + wr[112] * 9.5f;
    const float parCFR   =          wr[128] * 0.1f;
    const float parCWH   =          wr[144] * 0.2f;
    const float parC     =          wr[160];
    const float parTR    =          wr[176] * 20.0f;
    const float parAc    =          wr[192] * 2500.0f;

    // ---- regional flow (time-invariant per (g,m)) ----
    const float acm = ac[g];
    float regional_flow;
    {
        const float rf = fminf(fmaxf((acm - parAc) * 0.001f, -1.0f), 1.0f);
        if (acm < 2500.0f) {
            regional_flow = rf * parTR;
        } else {
            const float e = fminf(fmaxf(-(acm - 2500.0f) * (1.0f / 50.0f), -10.0f), 0.0f);
            regional_flow = expf(e) * parTR;
        }
    }

    const float invFC    = 1.0f / parFC;
    const float invLPFC  = 1.0f / (parLP * parFC);
    const float CFRCFMAX = parCFR * parCFMAX;
    const float oneMK1   = 1.0f - parK1;
    const float oneMK2   = 1.0f - parK2;
    const float negK0    = -parK0;

    float SNOWPACK = 0.001f, MELTWATER = 0.001f, SM = 0.001f, SUZ = 0.001f, SLZ = 0.001f;

    const float* xb = x + (size_t)g * 3;            // forcing base for this grid
    float* const outg = out + (size_t)blockIdx.x * 2; // warp's grid pair base

    // reduction job: lanes 0..9 -> (step jk, half jh)
    const int  jk = lane >> 1;
    const int  jh = lane & 1;
    const bool jactive = (lane < 10);

    // ---- one batch of TBATCH steps (compute + STS), then transpose-reduce ----
    auto do_batch = [&](const Forc& f, int tb, int buf) {
        #pragma unroll
        for (int k = 0; k < TBATCH; ++k) {
            const float Pm   = f.P[k];
            const float Tm   = f.T[k];
            const float PETm = f.E[k];

            // ---- snow routine (fused melt/refreeze net flux) ----
            const float dtt  = Tm - parTT;
            const bool  warm = (dtt >= 0.0f);
            const float RAIN = warm ? Pm : 0.0f;
            const float SP1  = SNOWPACK + (Pm - RAIN);
            const float coef = warm ? parCFMAX : CFRCFMAX;
            const float net  = fminf(fmaxf(coef * dtt, -MELTWATER), SP1);
            const float MW1  = MELTWATER + net;
            SNOWPACK = SP1 - net;
            const float tosoil = fmaxf(MW1 - parCWH * SNOWPACK, 0.0f);
            MELTWATER = MW1 - tosoil;

            // ---- soil routine ----
            const float pw  = __powf(SM * invFC, parBETA);
            const float soil_wetness = fminf(pw, 1.0f);
            const float omw = fmaxf(1.0f - pw, 0.0f);   // == 1 - min(pw,1)
            const float rt  = RAIN + tosoil;
            const float SM1 = fmaf(rt, omw, SM);        // SM + rt - rt*wetness
            const float SM2 = fminf(SM1, parFC);        // SM after excess removal
            const float excess = SM1 - SM2;             // == max(SM1-FC,0) (Sterbenz-exact)
            const float evapfactor = fminf(__powf(SM2 * invLPFC, parBETAET), 1.0f);
            const float SM3 = fmaxf(SM2 - PETm * evapfactor, NEARZERO);
            // 1 - min(SM/FC,1) == max(1 - SM*invFC, 0)
            const float capfac = fmaxf(fmaf(-SM3, invFC, 1.0f), 0.0f);
            const float capillary = (parC * SLZ) * capfac;
            SM = SM3 + capillary;                       // >= NEARZERO provably: clamp dead
            SLZ = fmaxf(SLZ - capillary, NEARZERO);

            // ---- response routine (FFMA-contracted) ----
            const float SUZa = fmaf(rt, soil_wetness, SUZ);   // SUZ + recharge
            const float SUZb = SUZa + excess;
            const float PERC = fminf(SUZb, parPERC);
            const float SUZc = SUZb - PERC;
            const float u    = fmaxf(SUZc - parUZL, 0.0f);
            const float SUZd = fmaf(negK0, u, SUZc);          // SUZ - Q0
            SUZ = SUZd * oneMK1;                              // SUZ - Q1
            const float SLZa = fmaxf(SLZ + PERC + regional_flow, 0.0f);
            SLZ = SLZa * oneMK2;                              // SLZ - Q2
            // q = Q0 + Q1 + Q2 = K0*u + K1*SUZd + K2*SLZa
            const float q = fmaf(parK0, u, fmaf(parK1, SUZd, parK2 * SLZa));

            red[buf][k * RSTRIDE + lane] = q;
        }

        __syncthreads();   // single-warp BAR (~3 cyc), drains STS

        // lanes 0..9: each sums one (step, grid-half) row of 16 floats
        if (jactive) {
            const float4* p = reinterpret_cast<const float4*>(
                &red[buf][jk * RSTRIDE + jh * 16]);
            const float4 a = p[0], b = p[1], c = p[2], d = p[3];
            const float4 s0 = make_float4(a.x + b.x, a.y + b.y, a.z + b.z, a.w + b.w);
            const float4 s1 = make_float4(c.x + d.x, c.y + d.y, c.z + d.z, c.w + d.w);
            const float sum = ((s0.x + s1.x) + (s0.y + s1.y))
                            + ((s0.z + s1.z) + (s0.w + s1.w));
            outg[((size_t)tb * TBATCH + jk) * NGRID + jh] = sum * (1.0f / 16.0f);
        }
    };

    // ---- software-pipelined main loop with ping-pong forcing buffers ----
    Forc A, B;
    load_batch(xb, 0, A);
    load_batch(xb, 1, B);

    #pragma unroll 1
    for (int tb = 0; tb < NBATCH - 1; tb += 2) {
        do_batch(A, tb, 0);
        load_batch(xb, tb + 2, A);                       // tb+2 <= 72, always valid
        do_batch(B, tb + 1, 1);
        const int nb = (tb + 3 <= NBATCH - 1) ? (tb + 3) : (NBATCH - 1);
        load_batch(xb, nb, B);                           // clamped (last iter redundant)
    }
    do_batch(A, NBATCH - 1, 0);                          // batch 72, loaded at tb=70
}

extern "C" void kernel_launch(void* const* d_in, const int* in_sizes, int n_in,
                              void* d_out, int out_size) {
    const float* x  = nullptr;
    const float* pr = nullptr;
    const float* wr = nullptr;
    const float* ac = nullptr;
    for (int i = 0; i < n_in; ++i) {
        const long n = (long)in_sizes[i];
        if      (n == 365L * NGRID * 3)            x  = (const float*)d_in[i];
        else if (n == 365L * NGRID * 3 * NMUL)     pr = (const float*)d_in[i];
        else if (n == (long)NGRID * 13 * NMUL)     wr = (const float*)d_in[i];
        else if (n == (long)NGRID)                 ac = (const float*)d_in[i];
    }
    // measured-best geometry: one warp per block, 5000 blocks (covers 160000 threads exactly)
    hbv_waterloss_kernel<<<5000, 32>>>(x, pr, wr, ac, (float*)d_out);
}

// round 15
// speedup vs baseline: 1.0225x; 1.0225x over previous
#include <cuda_runtime.h>

#define NGRID 10000
#define NSTEP 365
#define NMUL 16
#define NEARZERO 1e-5f
#define TBATCH 5            // 365 = 5 * 73
#define NBATCH (NSTEP / TBATCH)
#define XSTRIDE (NGRID * 3)
#define RSTRIDE 36          // smem row stride (floats): 32 data + 4 pad

__global__ __launch_bounds__(32)
void hbv_waterloss_kernel(
    const float* __restrict__ x,     // (365, 10000, 3) P,T,PET
    const float* __restrict__ praw,  // (365, 10000, 3, 16) -- only step 364 used
    const float* __restrict__ wraw,  // (10000, 13, 16)
    const float* __restrict__ ac,    // (10000,)
    float* __restrict__ out)         // (365, 10000)
{
    __shared__ float red[2][TBATCH * RSTRIDE];

    const int lane = threadIdx.x;                  // 0..31
    const int tid  = blockIdx.x * 32 + lane;
    const int g = tid >> 4;        // grid cell (lanes 0-15 -> g0, 16-31 -> g0+1)
    const int m = tid & 15;        // multiplier index

    // ---- parameter scaling (HBV params from last timestep: static_idx = -1) ----
    const float* pr = praw + ((size_t)364 * NGRID + g) * (3 * NMUL) + m;
    const float parBETA   = 1.0f  + pr[0]      * 5.0f;
    const float parK0     = 0.05f + pr[16]     * 0.85f;
    const float parBETAET = 0.3f  + pr[32]     * 4.7f;

    const float* wr = wraw + (size_t)g * (13 * NMUL) + m;
    const float parFC    = 50.0f  + wr[0]   * 950.0f;
    const float parK1    = 0.01f  + wr[16]  * 0.49f;
    const float parK2    = 0.001f + wr[32]  * 0.199f;
    const float parLP    = 0.2f   + wr[48]  * 0.8f;
    const float parPERC  =          wr[64]  * 10.0f;
    const float parUZL   =          wr[80]  * 100.0f;
    const float parTT    = -2.5f  + wr[96]  * 5.0f;
    const float parCFMAX = 0.5f   + wr[112] * 9.5f;
    const float parCFR   =          wr[128] * 0.1f;
    const float parCWH   =          wr[144] * 0.2f;
    const float parC     =          wr[160];
    const float parTR    =          wr[176] * 20.0f;
    const float parAc    =          wr[192] * 2500.0f;

    // ---- regional flow (time-invariant per (g,m)) ----
    const float acm = ac[g];
    float regional_flow;
    {
        const float rf = fminf(fmaxf((acm - parAc) * 0.001f, -1.0f), 1.0f);
        if (acm < 2500.0f) {
            regional_flow = rf * parTR;
        } else {
            const float e = fminf(fmaxf(-(acm - 2500.0f) * (1.0f / 50.0f), -10.0f), 0.0f);
            regional_flow = expf(e) * parTR;
        }
    }

    const float invFC    = 1.0f / parFC;
    const float invLPFC  = 1.0f / (parLP * parFC);
    const float CFRCFMAX = parCFR * parCFMAX;
    const float oneMK1   = 1.0f - parK1;
    const float oneMK2   = 1.0f - parK2;
    const float negK0    = -parK0;

    float SNOWPACK = 0.001f, MELTWATER = 0.001f, SM = 0.001f, SUZ = 0.001f, SLZ = 0.001f;

    const float* xb = x + (size_t)g * 3;              // forcing base for this grid
    float* const outg = out + (size_t)blockIdx.x * 2; // warp's grid pair base

    // reduction job: lanes 0..9 -> (step jk, half jh)
    const int  jk = lane >> 1;
    const int  jh = lane & 1;
    const bool jactive = (lane < 10);

    // ---- single forcing buffer (15 regs); prologue: load batch 0 ----
    float fP[TBATCH], fT[TBATCH], fE[TBATCH];
    {
        const float* a = xb;
        #pragma unroll
        for (int k = 0; k < TBATCH; ++k) {
            fP[k] = __ldg(a + 0);
            fT[k] = __ldg(a + 1);
            fE[k] = __ldg(a + 2);
            a += XSTRIDE;
        }
    }
    // xn: base of the NEXT batch to prefetch (clamped at the end)
    const float* xn = xb + (size_t)TBATCH * XSTRIDE;

    #pragma unroll 1
    for (int tb = 0; tb < NBATCH; ++tb) {
        const int buf = tb & 1;

        #pragma unroll
        for (int k = 0; k < TBATCH; ++k) {
            // consume this batch's forcing, then immediately reload the slot
            // for the next batch (full-batch latency coverage, single buffer)
            const float Pm   = fP[k];
            const float Tm   = fT[k];
            const float PETm = fE[k];
            {
                const float* a = xn + (size_t)k * XSTRIDE;
                fP[k] = __ldg(a + 0);
                fT[k] = __ldg(a + 1);
                fE[k] = __ldg(a + 2);
            }

            // ---- snow routine (fused melt/refreeze net flux) ----
            const float dtt  = Tm - parTT;
            const bool  warm = (dtt >= 0.0f);
            const float RAIN = warm ? Pm : 0.0f;
            const float SP1  = SNOWPACK + (Pm - RAIN);
            const float coef = warm ? parCFMAX : CFRCFMAX;
            const float net  = fminf(fmaxf(coef * dtt, -MELTWATER), SP1);
            const float MW1  = MELTWATER + net;
            SNOWPACK = SP1 - net;
            const float tosoil = fmaxf(MW1 - parCWH * SNOWPACK, 0.0f);
            MELTWATER = MW1 - tosoil;

            // ---- soil routine ----
            const float pw  = __powf(SM * invFC, parBETA);
            const float soil_wetness = fminf(pw, 1.0f);
            const float omw = fmaxf(1.0f - pw, 0.0f);   // == 1 - min(pw,1)
            const float rt  = RAIN + tosoil;
            const float SM1 = fmaf(rt, omw, SM);        // SM + rt - rt*wetness
            const float SM2 = fminf(SM1, parFC);        // SM after excess removal
            const float excess = SM1 - SM2;             // == max(SM1-FC,0) (Sterbenz-exact)
            const float evapfactor = fminf(__powf(SM2 * invLPFC, parBETAET), 1.0f);
            const float SM3 = fmaxf(SM2 - PETm * evapfactor, NEARZERO);
            const float capfac = fmaxf(fmaf(-SM3, invFC, 1.0f), 0.0f);
            const float capillary = (parC * SLZ) * capfac;
            SM = SM3 + capillary;                       // >= NEARZERO provably: clamp dead
            SLZ = fmaxf(SLZ - capillary, NEARZERO);

            // ---- response routine (FFMA-contracted) ----
            const float SUZa = fmaf(rt, soil_wetness, SUZ);   // SUZ + recharge
            const float SUZb = SUZa + excess;
            const float PERC = fminf(SUZb, parPERC);
            const float SUZc = SUZb - PERC;
            const float u    = fmaxf(SUZc - parUZL, 0.0f);
            const float SUZd = fmaf(negK0, u, SUZc);          // SUZ - Q0
            SUZ = SUZd * oneMK1;                              // SUZ - Q1
            const float SLZa = fmaxf(SLZ + PERC + regional_flow, 0.0f);
            SLZ = SLZa * oneMK2;                              // SLZ - Q2
            const float q = fmaf(parK0, u, fmaf(parK1, SUZd, parK2 * SLZa));

            red[buf][k * RSTRIDE + lane] = q;
        }

        __syncthreads();   // single-warp BAR (~3 cyc), drains STS

        // lanes 0..9: each sums one (step, grid-half) row of 16 floats
        if (jactive) {
            const float4* p = reinterpret_cast<const float4*>(
                &red[buf][jk * RSTRIDE + jh * 16]);
            const float4 a = p[0], b = p[1], c = p[2], d = p[3];
            const float4 s0 = make_float4(a.x + b.x, a.y + b.y, a.z + b.z, a.w + b.w);
            const float4 s1 = make_float4(c.x + d.x, c.y + d.y, c.z + d.z, c.w + d.w);
            const float sum = ((s0.x + s1.x) + (s0.y + s1.y))
                            + ((s0.z + s1.z) + (s0.w + s1.w));
            outg[((size_t)tb * TBATCH + jk) * NGRID + jh] = sum * (1.0f / 16.0f);
        }

        // advance prefetch base; clamp so the last batch redundantly reloads itself
        if (tb + 2 < NBATCH) xn += (size_t)TBATCH * XSTRIDE;
    }
}

extern "C" void kernel_launch(void* const* d_in, const int* in_sizes, int n_in,
                              void* d_out, int out_size) {
    const float* x  = nullptr;
    const float* pr = nullptr;
    const float* wr = nullptr;
    const float* ac = nullptr;
    for (int i = 0; i < n_in; ++i) {
        const long n = (long)in_sizes[i];
        if      (n == 365L * NGRID * 3)            x  = (const float*)d_in[i];
        else if (n == 365L * NGRID * 3 * NMUL)     pr = (const float*)d_in[i];
        else if (n == (long)NGRID * 13 * NMUL)     wr = (const float*)d_in[i];
        else if (n == (long)NGRID)                 ac = (const float*)d_in[i];
    }
    // measured-best geometry: one warp per block, 5000 blocks (covers 160000 threads exactly)
    hbv_waterloss_kernel<<<5000, 32>>>(x, pr, wr, ac, (float*)d_out);
}